// round 16
// baseline (speedup 1.0000x reference)
#include <cuda_runtime.h>
#include <cstdint>

// Grid is 128^3 logical; density padded to 130^3 (1-voxel zero border).
#define GRID_N (128*128*128)          // 2,097,152
#define PADW   130
#define PGRID_N (PADW*PADW*PADW)      // 2,197,000
#define SCAN_BLOCKS 1024              // 1024 * 256 * 8 = 2,097,152

#define FLAG_A (1ULL << 62)
#define FLAG_P (1ULL << 63)

__device__ __align__(16) float g_pdensity[PGRID_N];
__device__ __align__(16) unsigned g_tapmask[GRID_N];   // bit t: tap t nonzero
__device__ volatile unsigned long long g_status[SCAN_BLOCKS];
__device__ unsigned g_count;
__device__ unsigned g_cells[GRID_N];
__device__ unsigned g_cmask[GRID_N];                   // compacted tap masks

// tap offsets in padded grid: di*16900 + dj*130 + dk, t=(di+1)*9+(dj+1)*3+(dk+1)
__constant__ int c_off[27] = {
    -17031,-17030,-17029,-16901,-16900,-16899,-16771,-16770,-16769,
      -131,  -130,  -129,    -1,     0,     1,   129,   130,   131,
     16769, 16770, 16771, 16899, 16900, 16901, 17029, 17030, 17031};

// streaming (evict-first) stores: output is write-once, never re-read
__device__ __forceinline__ void stcs64(void* p, unsigned long long v) {
    asm volatile("st.global.cs.b64 [%0], %1;" :: "l"(p), "l"(v) : "memory");
}
__device__ __forceinline__ void stcs128(void* p, float4 v) {
    asm volatile("st.global.cs.v4.f32 [%0], {%1,%2,%3,%4};"
                 :: "l"(p), "f"(v.x), "f"(v.y), "f"(v.z), "f"(v.w) : "memory");
}
__device__ __forceinline__ void stcs32(void* p, float v) {
    asm volatile("st.global.cs.f32 [%0], %1;" :: "l"(p), "f"(v) : "memory");
}

// ---------------------------------------------------------------------------
// Scatter density + per-neighbor-cell nonzero-tap bitmask. Also clears the
// scan status array (runs before the scan kernel in stream order).
__global__ void scatter_kernel(const int* __restrict__ idx,
                               const float* __restrict__ feat, int n) {
    int i = blockIdx.x * blockDim.x + threadIdx.x;
    if (i < SCAN_BLOCKS) g_status[i] = 0ULL;
    if (i >= n) return;
    int x = idx[3*i], y = idx[3*i+1], z = idx[3*i+2];
    int plin = ((x + 1) * PADW + (y + 1)) * PADW + (z + 1);
    atomicAdd(&g_pdensity[plin], feat[i]);
    #pragma unroll
    for (int di = -1; di <= 1; di++)
        #pragma unroll
        for (int dj = -1; dj <= 1; dj++)
            #pragma unroll
            for (int dk = -1; dk <= 1; dk++) {
                int nx = x + di, ny = y + dj, nz = z + dk;
                if ((unsigned)nx < 128u && (unsigned)ny < 128u && (unsigned)nz < 128u) {
                    int t = (1 - di) * 9 + (1 - dj) * 3 + (1 - dk);
                    atomicOr(&g_tapmask[(nx << 14) | (ny << 7) | nz], 1u << t);
                }
            }
}

// ---------------------------------------------------------------------------
// Single-pass scan + compaction with decoupled lookback.
__global__ void scan_kernel() {
    unsigned lane = threadIdx.x & 31, wid = threadIdx.x >> 5;

    int base = blockIdx.x * 2048 + threadIdx.x * 8;
    const uint4* P4 = (const uint4*)(g_tapmask + base);
    uint4 a = P4[0], b4 = P4[1];
    unsigned m[8] = {a.x, a.y, a.z, a.w, b4.x, b4.y, b4.z, b4.w};
    unsigned s = 0;
    #pragma unroll
    for (int i = 0; i < 8; i++) s += (m[i] != 0);

    unsigned incl = s;
    #pragma unroll
    for (int o = 1; o < 32; o <<= 1) {
        unsigned t = __shfl_up_sync(0xFFFFFFFFu, incl, o);
        if (lane >= (unsigned)o) incl += t;
    }
    unsigned excl = incl - s;
    __shared__ unsigned ws[8];
    __shared__ unsigned s_bof, s_tot;
    if (lane == 31) ws[wid] = incl;
    __syncthreads();

    if (threadIdx.x == 0) {
        unsigned tot = 0;
        #pragma unroll
        for (int i = 0; i < 8; i++) tot += ws[i];
        s_tot = tot;
        g_status[blockIdx.x] = (blockIdx.x == 0 ? FLAG_P : FLAG_A)
                             | (unsigned long long)tot;
    }
    __syncthreads();

    // warp 0: decoupled lookback over predecessors
    if (wid == 0) {
        unsigned running = 0;
        int idx = (int)blockIdx.x - 1;
        while (idx >= 0) {
            int my = idx - (int)lane;
            unsigned long long st = (my >= 0) ? g_status[my] : FLAG_P;
            unsigned fP = __ballot_sync(0xFFFFFFFFu, (st & FLAG_P) != 0ULL);
            unsigned f0 = __ballot_sync(0xFFFFFFFFu,
                                        my >= 0 && (st & (FLAG_P | FLAG_A)) == 0ULL);
            int lp = fP ? (__ffs(fP) - 1) : 32;
            unsigned need = (lp >= 31) ? 0xFFFFFFFFu : ((1u << (lp + 1)) - 1u);
            if (f0 & need) { __nanosleep(40); continue; }   // retry same idx
            unsigned val = (unsigned)(st & 0xFFFFFFFFu);
            unsigned contrib = ((int)lane <= lp && my >= 0) ? val : 0u;
            running += __reduce_add_sync(0xFFFFFFFFu, contrib);
            if (lp < 32) break;
            idx -= 32;
        }
        if (lane == 0) {
            s_bof = running;
            g_status[blockIdx.x] = FLAG_P
                                 | (unsigned long long)(running + s_tot);
            if (blockIdx.x == SCAN_BLOCKS - 1) g_count = running + s_tot;
        }
    }
    __syncthreads();
    unsigned bof = s_bof;

    unsigned woff = 0;
    for (unsigned i = 0; i < wid; i++) woff += ws[i];
    unsigned pos = bof + woff + excl;
    #pragma unroll
    for (int i = 0; i < 8; i++) {
        if (m[i] != 0) {
            g_cells[pos] = (unsigned)(base + i);
            g_cmask[pos] = m[i];
            pos++;
        }
    }
}

// ---- sparse-tap feature writer ------------------------------------------
// Packed dual-fp32 FMA (sm_100+).
__device__ __forceinline__ void fma_x2(unsigned long long& d,
                                       unsigned long long a,
                                       unsigned long long b) {
    asm("fma.rn.f32x2 %0, %1, %2, %0;" : "+l"(d) : "l"(a), "l"(b));
}
__device__ __forceinline__ unsigned long long pack2(float f) {
    unsigned u = __float_as_uint(f);
    return ((unsigned long long)u << 32) | u;
}

// One tap contribution: broadcast density from lane t, weight pair from smem.
__device__ __forceinline__ void tap_fma(unsigned long long& acc, float rv, int t,
                                        const float* KsL) {
    float dv = __shfl_sync(0xFFFFFFFFu, rv, t);
    unsigned long long dd = pack2(dv);
    unsigned long long kv = *(const unsigned long long*)(KsL + t * 64);
    fma_x2(acc, kv, dd);
}

// Warp = 32 consecutive ranks, lane = 2 output channels. The precomputed
// tap mask drives a predicated gather of only the ~1.31 nonzero taps.
// Chunks of 8 cells, double-buffered; masks re-shuffled on demand (no
// mask buffers -> fewer regs -> higher occupancy).
__global__ void __launch_bounds__(256, 5)
feat_kernel(const float* __restrict__ kw,
            float* __restrict__ outc,   // [rows,3] coords (may be null)
            float* __restrict__ outf,   // [rows,64] features (may be null)
            int rows) {
    __shared__ float Ks[27 * 64];
    for (int i = threadIdx.x; i < 27 * 64; i += 256) Ks[i] = kw[i];
    __syncthreads();

    int lane = threadIdx.x & 31;
    int wid = threadIdx.x >> 5;
    int base_r = (blockIdx.x * 8 + wid) * 32;
    if (base_r >= rows) return;
    unsigned M = g_count;

    // per-lane own cell: coords + mask + density base
    int r_me = base_r + lane;
    bool act = (r_me < (int)M);
    unsigned lin = act ? g_cells[r_me] : 0u;
    unsigned msk = act ? g_cmask[r_me] : 0u;
    int x = lin >> 14, y = (lin >> 7) & 127, z = lin & 127;
    if (outc && r_me < rows) {
        stcs32(outc + 3*r_me + 0, act ? (float)x : 128.0f);
        stcs32(outc + 3*r_me + 1, act ? (float)y : 128.0f);
        stcs32(outc + 3*r_me + 2, act ? (float)z : 128.0f);
    }
    if (!outf) return;

    // fully-inactive warp: flat zero-fill of 32 rows (8 KB)
    if (base_r >= (int)M) {
        float4 z4 = make_float4(0.f, 0.f, 0.f, 0.f);
        if (base_r + 32 <= rows) {
            float4* o = (float4*)(outf + (size_t)base_r * 64);
            #pragma unroll
            for (int i = 0; i < 16; i++) stcs128(o + lane + i * 32, z4);
        } else {
            for (int c = 0; c < 32; c++) {
                int r = base_r + c;
                if (r < rows)
                    stcs64(outf + (size_t)r * 64 + lane * 2, 0ULL);
            }
        }
        return;
    }

    int base_l = ((x + 1) * PADW + (y + 1)) * PADW + (z + 1);
    int myoff = c_off[lane < 27 ? lane : 13];
    const float* D = g_pdensity;
    const float* KsL = Ks + lane * 2;

    // double-buffered chunks of 8 cells; loads predicated by the tap mask
    float bufA[8], bufB[8];
    #pragma unroll
    for (int j = 0; j < 8; j++) {
        int bc = __shfl_sync(0xFFFFFFFFu, base_l, j);
        unsigned mc = __shfl_sync(0xFFFFFFFFu, msk, j);
        bufA[j] = ((mc >> lane) & 1u) ? D[bc + myoff] : 0.0f;
    }
    #pragma unroll
    for (int c8 = 0; c8 < 4; c8++) {
        float* cur = (c8 & 1) ? bufB : bufA;
        float* nxt = (c8 & 1) ? bufA : bufB;
        if (c8 < 3) {
            #pragma unroll
            for (int j = 0; j < 8; j++) {
                int bc = __shfl_sync(0xFFFFFFFFu, base_l, (c8 + 1) * 8 + j);
                unsigned mc = __shfl_sync(0xFFFFFFFFu, msk, (c8 + 1) * 8 + j);
                nxt[j] = ((mc >> lane) & 1u) ? D[bc + myoff] : 0.0f;
            }
        }
        #pragma unroll
        for (int j = 0; j < 8; j++) {
            int r = base_r + c8 * 8 + j;
            float rv = cur[j];
            unsigned m = __shfl_sync(0xFFFFFFFFu, msk, c8 * 8 + j);
            unsigned long long acc = 0ULL;
            if (m) {                          // warp-uniform branches
                int t0 = __ffs(m) - 1; m &= m - 1;
                tap_fma(acc, rv, t0, KsL);
                if (m) {                      // ~30% of active cells
                    int t1 = __ffs(m) - 1; m &= m - 1;
                    tap_fma(acc, rv, t1, KsL);
                    while (m) {               // rare: >=3 nonzero taps
                        int t = __ffs(m) - 1; m &= m - 1;
                        tap_fma(acc, rv, t, KsL);
                    }
                }
            }
            if (r < rows)
                stcs64(outf + (size_t)r * 64 + lane * 2, acc);
        }
    }
}

// ---------------------------------------------------------------------------
extern "C" void kernel_launch(void* const* d_in, const int* in_sizes, int n_in,
                              void* d_out, int out_size) {
    const int*   indices  = (const int*)d_in[0];    // [N,3] int32
    const float* features = (const float*)d_in[1];  // [N,1] float32
    const float* kw       = (const float*)d_in[2];  // [3,3,3,1,64] float32

    int n = in_sizes[0] / 3;
    int rows = n * 27;
    float* out = (float*)d_out;

    // zero density + tap masks via memset nodes
    void* p_density = nullptr;
    void* p_tapmask = nullptr;
    cudaGetSymbolAddress(&p_density, g_pdensity);
    cudaGetSymbolAddress(&p_tapmask, g_tapmask);
    cudaMemsetAsync(p_density, 0, PGRID_N * sizeof(float));
    cudaMemsetAsync(p_tapmask, 0, GRID_N * sizeof(unsigned));

    scatter_kernel<<<(n + 255) / 256, 256>>>(indices, features, n);
    scan_kernel<<<SCAN_BLOCKS, 256>>>();

    float* outc0 = nullptr; float* outf0 = nullptr;
    if (out_size == rows * 64) {
        outf0 = out;
    } else if (out_size == rows * 3) {
        outc0 = out;
    } else {
        outc0 = out; outf0 = out + (size_t)rows * 3;
    }
    int blocks = (rows + 255) / 256;    // 8 warps/block, 32 rows/warp
    feat_kernel<<<blocks, 256>>>(kw, outc0, outf0, rows);
}

// round 17
// speedup vs baseline: 1.0719x; 1.0719x over previous
#include <cuda_runtime.h>
#include <cstdint>

// Grid is 128^3 logical; density padded to 130^3 (1-voxel zero border).
#define GRID_N (128*128*128)          // 2,097,152
#define PADW   130
#define PGRID_N (PADW*PADW*PADW)      // 2,197,000
#define SCAN_BLOCKS 1024              // 1024 * 256 * 8 = 2,097,152

__device__ __align__(16) float g_pdensity[PGRID_N];
__device__ __align__(16) unsigned g_tapmask[GRID_N];   // bit t: tap t nonzero
__device__ unsigned g_blocksums[SCAN_BLOCKS];
__device__ unsigned g_count;
__device__ unsigned g_cells[GRID_N];
__device__ unsigned g_cmask[GRID_N];                   // compacted tap masks

// tap offsets in padded grid: di*16900 + dj*130 + dk, t=(di+1)*9+(dj+1)*3+(dk+1)
__constant__ int c_off[27] = {
    -17031,-17030,-17029,-16901,-16900,-16899,-16771,-16770,-16769,
      -131,  -130,  -129,    -1,     0,     1,   129,   130,   131,
     16769, 16770, 16771, 16899, 16900, 16901, 17029, 17030, 17031};

// streaming (evict-first) stores: output is write-once, never re-read
__device__ __forceinline__ void stcs64(void* p, unsigned long long v) {
    asm volatile("st.global.cs.b64 [%0], %1;" :: "l"(p), "l"(v) : "memory");
}
__device__ __forceinline__ void stcs128(void* p, float4 v) {
    asm volatile("st.global.cs.v4.f32 [%0], {%1,%2,%3,%4};"
                 :: "l"(p), "f"(v.x), "f"(v.y), "f"(v.z), "f"(v.w) : "memory");
}
__device__ __forceinline__ void stcs32(void* p, float v) {
    asm volatile("st.global.cs.f32 [%0], %1;" :: "l"(p), "f"(v) : "memory");
}

// ---------------------------------------------------------------------------
// Parallel scatter: one thread per (point, tap). 27x the parallelism of the
// per-point version (1.35M threads); spread-address L2 atomics at full rate.
__global__ void scatter_kernel(const int* __restrict__ idx,
                               const float* __restrict__ feat, long long total) {
    long long tid = (long long)blockIdx.x * blockDim.x + threadIdx.x;
    if (tid >= total) return;
    int i = (int)(tid / 27);
    int t = (int)(tid - (long long)i * 27);
    int x = idx[3*i], y = idx[3*i+1], z = idx[3*i+2];
    int di = 1 - t / 9, dj = 1 - (t % 9) / 3, dk = 1 - t % 3;
    int nx = x + di, ny = y + dj, nz = z + dk;
    if (t == 13) {  // center: also accumulate density
        int plin = ((x + 1) * PADW + (y + 1)) * PADW + (z + 1);
        atomicAdd(&g_pdensity[plin], feat[i]);
    }
    if ((unsigned)nx < 128u && (unsigned)ny < 128u && (unsigned)nz < 128u)
        atomicOr(&g_tapmask[(nx << 14) | (ny << 7) | nz], 1u << t);
}

// ---- prefix scan over 2M masks: 2 kernels -------------------------------
__global__ void scan1_kernel() {
    int base = blockIdx.x * 2048 + threadIdx.x * 8;
    const uint4* P = (const uint4*)(g_tapmask + base);
    uint4 a = P[0], b = P[1];
    unsigned s = (a.x != 0) + (a.y != 0) + (a.z != 0) + (a.w != 0)
               + (b.x != 0) + (b.y != 0) + (b.z != 0) + (b.w != 0);
    #pragma unroll
    for (int o = 16; o; o >>= 1) s += __shfl_down_sync(0xFFFFFFFFu, s, o);
    __shared__ unsigned ws[8];
    if ((threadIdx.x & 31) == 0) ws[threadIdx.x >> 5] = s;
    __syncthreads();
    if (threadIdx.x == 0) {
        unsigned t = 0;
        #pragma unroll
        for (int i = 0; i < 8; i++) t += ws[i];
        g_blocksums[blockIdx.x] = t;
    }
}

// Fused scan2+scan3: each block redundantly computes its global offset from
// the 1024 block sums, then compacts its 2048 cells (id + mask).
__global__ void scan23_kernel() {
    unsigned lane = threadIdx.x & 31, wid = threadIdx.x >> 5;

    unsigned partial = 0;
    for (unsigned i = threadIdx.x; i < blockIdx.x; i += 256)
        partial += g_blocksums[i];
    #pragma unroll
    for (int o = 16; o; o >>= 1) partial += __shfl_down_sync(0xFFFFFFFFu, partial, o);
    __shared__ unsigned sred[8];
    __shared__ unsigned s_bof;
    if (lane == 0) sred[wid] = partial;
    __syncthreads();
    if (threadIdx.x == 0) {
        unsigned t = 0;
        #pragma unroll
        for (int i = 0; i < 8; i++) t += sred[i];
        s_bof = t;
    }
    __syncthreads();
    unsigned bof = s_bof;

    int base = blockIdx.x * 2048 + threadIdx.x * 8;
    const uint4* P = (const uint4*)(g_tapmask + base);
    uint4 a = P[0], b = P[1];
    unsigned m[8] = {a.x, a.y, a.z, a.w, b.x, b.y, b.z, b.w};
    unsigned s = 0;
    #pragma unroll
    for (int i = 0; i < 8; i++) s += (m[i] != 0);

    unsigned incl = s;
    #pragma unroll
    for (int o = 1; o < 32; o <<= 1) {
        unsigned t = __shfl_up_sync(0xFFFFFFFFu, incl, o);
        if (lane >= (unsigned)o) incl += t;
    }
    unsigned excl = incl - s;
    __shared__ unsigned ws[8];
    if (lane == 31) ws[wid] = incl;
    __syncthreads();
    unsigned woff = 0;
    for (unsigned i = 0; i < wid; i++) woff += ws[i];
    unsigned pos = bof + woff + excl;
    #pragma unroll
    for (int i = 0; i < 8; i++) {
        if (m[i] != 0) {
            g_cells[pos] = (unsigned)(base + i);
            g_cmask[pos] = m[i];
            pos++;
        }
    }
    if (blockIdx.x == SCAN_BLOCKS - 1 && threadIdx.x == 255)
        g_count = bof + woff + incl;
}

// ---- sparse-tap feature writer ------------------------------------------
// Packed dual-fp32 FMA (sm_100+).
__device__ __forceinline__ void fma_x2(unsigned long long& d,
                                       unsigned long long a,
                                       unsigned long long b) {
    asm("fma.rn.f32x2 %0, %1, %2, %0;" : "+l"(d) : "l"(a), "l"(b));
}
__device__ __forceinline__ unsigned long long pack2(float f) {
    unsigned u = __float_as_uint(f);
    return ((unsigned long long)u << 32) | u;
}

// One tap contribution: broadcast density from lane t, weight pair from smem.
__device__ __forceinline__ void tap_fma(unsigned long long& acc, float rv, int t,
                                        const float* KsL) {
    float dv = __shfl_sync(0xFFFFFFFFu, rv, t);
    unsigned long long dd = pack2(dv);
    unsigned long long kv = *(const unsigned long long*)(KsL + t * 64);
    fma_x2(acc, kv, dd);
}

// Warp = 32 consecutive ranks, lane = 2 output channels. The precomputed
// tap mask drives a predicated gather of only the ~1.31 nonzero taps.
// Chunks of 8 cells, double-buffered. (Exact R15 shape: measured 72.2us.)
__global__ void __launch_bounds__(256)
feat_kernel(const float* __restrict__ kw,
            float* __restrict__ outc,   // [rows,3] coords (may be null)
            float* __restrict__ outf,   // [rows,64] features (may be null)
            int rows) {
    __shared__ float Ks[27 * 64];
    for (int i = threadIdx.x; i < 27 * 64; i += 256) Ks[i] = kw[i];
    __syncthreads();

    int lane = threadIdx.x & 31;
    int wid = threadIdx.x >> 5;
    int base_r = (blockIdx.x * 8 + wid) * 32;
    if (base_r >= rows) return;
    unsigned M = g_count;

    // per-lane own cell: coords + mask + density base
    int r_me = base_r + lane;
    bool act = (r_me < (int)M);
    unsigned lin = act ? g_cells[r_me] : 0u;
    unsigned msk = act ? g_cmask[r_me] : 0u;
    int x = lin >> 14, y = (lin >> 7) & 127, z = lin & 127;
    if (outc && r_me < rows) {
        stcs32(outc + 3*r_me + 0, act ? (float)x : 128.0f);
        stcs32(outc + 3*r_me + 1, act ? (float)y : 128.0f);
        stcs32(outc + 3*r_me + 2, act ? (float)z : 128.0f);
    }
    if (!outf) return;

    // fully-inactive warp: flat zero-fill of 32 rows (8 KB)
    if (base_r >= (int)M) {
        float4 z4 = make_float4(0.f, 0.f, 0.f, 0.f);
        if (base_r + 32 <= rows) {
            float4* o = (float4*)(outf + (size_t)base_r * 64);
            #pragma unroll
            for (int i = 0; i < 16; i++) stcs128(o + lane + i * 32, z4);
        } else {
            for (int c = 0; c < 32; c++) {
                int r = base_r + c;
                if (r < rows)
                    stcs64(outf + (size_t)r * 64 + lane * 2, 0ULL);
            }
        }
        return;
    }

    int base_l = ((x + 1) * PADW + (y + 1)) * PADW + (z + 1);
    int myoff = c_off[lane < 27 ? lane : 13];
    const float* D = g_pdensity;
    const float* KsL = Ks + lane * 2;

    // double-buffered chunks of 8 cells; loads predicated by the tap mask
    float bufA[8], bufB[8];
    unsigned mA[8], mB[8];
    #pragma unroll
    for (int j = 0; j < 8; j++) {
        int bc = __shfl_sync(0xFFFFFFFFu, base_l, j);
        unsigned mc = __shfl_sync(0xFFFFFFFFu, msk, j);
        mA[j] = mc;
        bufA[j] = ((mc >> lane) & 1u) ? D[bc + myoff] : 0.0f;
    }
    #pragma unroll
    for (int c8 = 0; c8 < 4; c8++) {
        float* cur = (c8 & 1) ? bufB : bufA;
        float* nxt = (c8 & 1) ? bufA : bufB;
        unsigned* mcur = (c8 & 1) ? mB : mA;
        unsigned* mnxt = (c8 & 1) ? mA : mB;
        if (c8 < 3) {
            #pragma unroll
            for (int j = 0; j < 8; j++) {
                int bc = __shfl_sync(0xFFFFFFFFu, base_l, (c8 + 1) * 8 + j);
                unsigned mc = __shfl_sync(0xFFFFFFFFu, msk, (c8 + 1) * 8 + j);
                mnxt[j] = mc;
                nxt[j] = ((mc >> lane) & 1u) ? D[bc + myoff] : 0.0f;
            }
        }
        #pragma unroll
        for (int j = 0; j < 8; j++) {
            int r = base_r + c8 * 8 + j;
            float rv = cur[j];
            unsigned m = mcur[j];
            unsigned long long acc = 0ULL;
            if (m) {                          // warp-uniform branches
                int t0 = __ffs(m) - 1; m &= m - 1;
                tap_fma(acc, rv, t0, KsL);
                if (m) {                      // ~30% of active cells
                    int t1 = __ffs(m) - 1; m &= m - 1;
                    tap_fma(acc, rv, t1, KsL);
                    while (m) {               // rare: >=3 nonzero taps
                        int t = __ffs(m) - 1; m &= m - 1;
                        tap_fma(acc, rv, t, KsL);
                    }
                }
            }
            if (r < rows)
                stcs64(outf + (size_t)r * 64 + lane * 2, acc);
        }
    }
}

// ---------------------------------------------------------------------------
extern "C" void kernel_launch(void* const* d_in, const int* in_sizes, int n_in,
                              void* d_out, int out_size) {
    const int*   indices  = (const int*)d_in[0];    // [N,3] int32
    const float* features = (const float*)d_in[1];  // [N,1] float32
    const float* kw       = (const float*)d_in[2];  // [3,3,3,1,64] float32

    int n = in_sizes[0] / 3;
    int rows = n * 27;
    float* out = (float*)d_out;

    // zero density + tap masks via memset nodes
    void* p_density = nullptr;
    void* p_tapmask = nullptr;
    cudaGetSymbolAddress(&p_density, g_pdensity);
    cudaGetSymbolAddress(&p_tapmask, g_tapmask);
    cudaMemsetAsync(p_density, 0, PGRID_N * sizeof(float));
    cudaMemsetAsync(p_tapmask, 0, GRID_N * sizeof(unsigned));

    long long total = (long long)n * 27;
    int sblocks = (int)((total + 255) / 256);
    scatter_kernel<<<sblocks, 256>>>(indices, features, total);
    scan1_kernel<<<SCAN_BLOCKS, 256>>>();
    scan23_kernel<<<SCAN_BLOCKS, 256>>>();

    float* outc0 = nullptr; float* outf0 = nullptr;
    if (out_size == rows * 64) {
        outf0 = out;
    } else if (out_size == rows * 3) {
        outc0 = out;
    } else {
        outc0 = out; outf0 = out + (size_t)rows * 3;
    }
    int blocks = (rows + 255) / 256;    // 8 warps/block, 32 rows/warp
    feat_kernel<<<blocks, 256>>>(kw, outc0, outf0, rows);
}